// round 3
// baseline (speedup 1.0000x reference)
#include <cuda_runtime.h>
#include <math.h>

// Problem constants (fixed by the reference)
#define NEGV -999999.0f
constexpr int B  = 2;
constexpr int H  = 16;
constexpr int L  = 2048;
constexpr int D  = 64;
constexpr int BHN = B * H;       // 32
constexpr int BQ = 64;           // query tile
constexpr int BK = 64;           // key tile
constexpr int NT = 256;          // threads per block
constexpr int QS = 68;           // padded stride for [D][64] d-major tiles
constexpr int PSTR = 65;         // padded stride for P tile rows

// Scratch for the degenerate-row path: mean over all L values per (b,h,d).
__device__ float g_vmean[BHN * D];

// ---------------------------------------------------------------------------
// Kernel 1: per-(b,h) mean of values over the full sequence.
// Reference softmax over an all-masked row (score == NEG everywhere) is
// uniform over ALL 2048 keys -> output row = mean of all values.
// ---------------------------------------------------------------------------
__global__ void vmean_kernel(const float* __restrict__ v) {
    int bh  = blockIdx.x;
    int d   = threadIdx.x & 63;
    int grp = threadIdx.x >> 6;   // 0..3
    const float* vp = v + (size_t)bh * L * D;
    float s = 0.f;
    for (int kk = grp; kk < L; kk += 4)
        s += vp[(size_t)kk * D + d];
    __shared__ float red[4][64];
    red[grp][d] = s;
    __syncthreads();
    if (grp == 0) {
        float tot = red[0][d] + red[1][d] + red[2][d] + red[3][d];
        g_vmean[bh * D + d] = tot * (1.0f / (float)L);
    }
}

// ---------------------------------------------------------------------------
// Kernel 2: flash attention with bias + value mask + causal + query mask.
// Grid: (L/BQ, B*H). Block: 256 threads, each owns a 4x4 output micro-tile.
// Masks arrive as int32 (harness converts jax bool -> int32).
// ---------------------------------------------------------------------------
extern __shared__ float sm[];

__global__ void __launch_bounds__(NT)
attn_kernel(const float* __restrict__ q,
            const float* __restrict__ k,
            const float* __restrict__ v,
            const int* __restrict__ qmask,
            const int* __restrict__ vmask,
            const float* __restrict__ bias,
            float* __restrict__ out)
{
    const int qt = blockIdx.x;
    const int bh = blockIdx.y;
    const int q0 = qt * BQ;

    float* Qs = sm;                 // [D][QS] d-major Q tile
    float* KP = sm + D * QS;        // union: [D][QS] d-major K tile  |  [BQ][PSTR] P tile
    float* Vs = sm + 2 * D * QS;    // [BK][QS] row-major V tile
    int*   vm = (int*)(sm + 3 * D * QS);   // 64 ints

    const int tid = threadIdx.x;
    const int tx = tid & 15;        // output col group
    const int ty = tid >> 4;        // output row group

    // ---- load Q tile (transposed to d-major) ----
    const float* qb = q + ((size_t)bh * L + q0) * D;
    for (int idx = tid; idx < BQ * D / 4; idx += NT) {
        int r  = idx >> 4;          // 0..63
        int d4 = (idx & 15) * 4;
        float4 t = *(const float4*)(qb + (size_t)r * D + d4);
        Qs[(d4 + 0) * QS + r] = t.x;
        Qs[(d4 + 1) * QS + r] = t.y;
        Qs[(d4 + 2) * QS + r] = t.z;
        Qs[(d4 + 3) * QS + r] = t.w;
    }

    float m[4], lsum[4], O[4][4];
    #pragma unroll
    for (int r = 0; r < 4; ++r) {
        m[r] = -INFINITY; lsum[r] = 0.f;
        #pragma unroll
        for (int c = 0; c < 4; ++c) O[r][c] = 0.f;
    }

    for (int t = 0; t <= qt; ++t) {
        const int k0 = t * BK;
        __syncthreads();   // protect KP/Vs before overwrite; also covers Q load at t=0

        // ---- load K (d-major) and V (row-major) tiles + value mask ----
        const float* kb = k + ((size_t)bh * L + k0) * D;
        const float* vb = v + ((size_t)bh * L + k0) * D;
        for (int idx = tid; idx < BK * D / 4; idx += NT) {
            int r  = idx >> 4;
            int d4 = (idx & 15) * 4;
            float4 tk = *(const float4*)(kb + (size_t)r * D + d4);
            KP[(d4 + 0) * QS + r] = tk.x;
            KP[(d4 + 1) * QS + r] = tk.y;
            KP[(d4 + 2) * QS + r] = tk.z;
            KP[(d4 + 3) * QS + r] = tk.w;
            float4 tv = *(const float4*)(vb + (size_t)r * D + d4);
            *(float4*)(Vs + r * QS + d4) = tv;
        }
        if (tid < 64) vm[tid] = vmask[(size_t)bh * L + k0 + tid];
        __syncthreads();

        // ---- QK^T micro-GEMM ----
        float s[4][4];
        #pragma unroll
        for (int r = 0; r < 4; ++r)
            #pragma unroll
            for (int c = 0; c < 4; ++c) s[r][c] = 0.f;

        #pragma unroll 8
        for (int d = 0; d < D; ++d) {
            float4 qv = *(const float4*)(Qs + d * QS + ty * 4);
            float4 kv = *(const float4*)(KP + d * QS + tx * 4);
            float qa[4] = {qv.x, qv.y, qv.z, qv.w};
            float ka[4] = {kv.x, kv.y, kv.z, kv.w};
            #pragma unroll
            for (int r = 0; r < 4; ++r)
                #pragma unroll
                for (int c = 0; c < 4; ++c)
                    s[r][c] = fmaf(qa[r], ka[c], s[r][c]);
        }

        // ---- scale + bias + masks ----
        const bool diag = (t == qt);
        const float* brow = bias + ((size_t)(bh * L + q0)) * L + k0;
        #pragma unroll
        for (int r = 0; r < 4; ++r) {
            int row = ty * 4 + r;
            float4 bb = *(const float4*)(brow + (size_t)row * L + tx * 4);
            float bv[4] = {bb.x, bb.y, bb.z, bb.w};
            #pragma unroll
            for (int c = 0; c < 4; ++c) {
                int col = tx * 4 + c;
                float val = s[r][c] * 0.125f + bv[c];
                bool ok = (vm[col] != 0) && (!diag || (col <= row));
                s[r][c] = ok ? val : NEGV;
            }
        }

        // ---- online softmax update ----
        #pragma unroll
        for (int r = 0; r < 4; ++r) {
            float tm = fmaxf(fmaxf(s[r][0], s[r][1]), fmaxf(s[r][2], s[r][3]));
            #pragma unroll
            for (int off = 8; off > 0; off >>= 1)
                tm = fmaxf(tm, __shfl_xor_sync(0xffffffffu, tm, off));
            float mn = fmaxf(m[r], tm);
            float alpha = __expf(m[r] - mn);   // m=-inf first tile -> 0
            float rs = 0.f;
            #pragma unroll
            for (int c = 0; c < 4; ++c) {
                s[r][c] = __expf(s[r][c] - mn);  // all-NEG row -> exp(0)=1 (matches ref)
                rs += s[r][c];
            }
            #pragma unroll
            for (int off = 8; off > 0; off >>= 1)
                rs += __shfl_xor_sync(0xffffffffu, rs, off);
            lsum[r] = lsum[r] * alpha + rs;
            m[r] = mn;
            #pragma unroll
            for (int c = 0; c < 4; ++c) O[r][c] *= alpha;
        }

        __syncthreads();   // done reading KP as K

        // ---- stage P tile into smem (reuses K buffer) ----
        #pragma unroll
        for (int r = 0; r < 4; ++r)
            #pragma unroll
            for (int c = 0; c < 4; ++c)
                KP[(ty * 4 + r) * PSTR + tx * 4 + c] = s[r][c];
        __syncthreads();

        // ---- PV micro-GEMM: O += P @ V ----
        #pragma unroll 4
        for (int kk = 0; kk < BK; ++kk) {
            float4 vv = *(const float4*)(Vs + kk * QS + tx * 4);
            float va[4] = {vv.x, vv.y, vv.z, vv.w};
            float pv[4];
            #pragma unroll
            for (int r = 0; r < 4; ++r) pv[r] = KP[(ty * 4 + r) * PSTR + kk];
            #pragma unroll
            for (int r = 0; r < 4; ++r)
                #pragma unroll
                for (int c = 0; c < 4; ++c)
                    O[r][c] = fmaf(pv[r], va[c], O[r][c]);
        }
    }

    // ---- finalize: normalize, degenerate-row override, query mask, store ----
    #pragma unroll
    for (int r = 0; r < 4; ++r) {
        int row = q0 + ty * 4 + r;
        int qm = qmask[(size_t)bh * L + row];
        bool degen = (m[r] <= -999998.0f);   // whole causal region was value-masked
        float inv = 1.0f / lsum[r];
        float4 o;
        float ov[4];
        #pragma unroll
        for (int c = 0; c < 4; ++c) {
            float val = degen ? g_vmean[bh * D + tx * 4 + c] : O[r][c] * inv;
            ov[c] = qm ? val : 0.0f;
        }
        o.x = ov[0]; o.y = ov[1]; o.z = ov[2]; o.w = ov[3];
        *(float4*)(out + ((size_t)bh * L + row) * D + tx * 4) = o;
    }
}

// ---------------------------------------------------------------------------
// Launch
// ---------------------------------------------------------------------------
extern "C" void kernel_launch(void* const* d_in, const int* in_sizes, int n_in,
                              void* d_out, int out_size)
{
    const float* q   = (const float*)d_in[0];
    const float* k   = (const float*)d_in[1];
    const float* v   = (const float*)d_in[2];
    const int* qmask = (const int*)d_in[3];
    const int* vmask = (const int*)d_in[4];
    const float* bias = (const float*)d_in[5];
    float* out = (float*)d_out;

    size_t smem = (size_t)(3 * D * QS) * sizeof(float) + 64 * sizeof(int);
    cudaFuncSetAttribute(attn_kernel, cudaFuncAttributeMaxDynamicSharedMemorySize, (int)smem);

    vmean_kernel<<<BHN, 256>>>(v);
    dim3 grid(L / BQ, BHN);
    attn_kernel<<<grid, NT, smem>>>(q, k, v, qmask, vmask, bias, out);
}

// round 9
// speedup vs baseline: 1.6941x; 1.6941x over previous
#include <cuda_runtime.h>
#include <cuda_bf16.h>
#include <math.h>
#include <stdint.h>

#define NEGV -999999.0f
constexpr int B = 2, H = 16, L = 2048, D = 64, BHN = 32;
constexpr int NT = 256;

// Pre-split K (row-major [bh][key][d]) and V^T ([bh][d][key]) as bf16 hi/lo.
__device__ __align__(16) __nv_bfloat16 g_khi[(size_t)BHN * L * D];
__device__ __align__(16) __nv_bfloat16 g_klo[(size_t)BHN * L * D];
__device__ __align__(16) __nv_bfloat16 g_vthi[(size_t)BHN * D * L];
__device__ __align__(16) __nv_bfloat16 g_vtlo[(size_t)BHN * D * L];
__device__ float g_vmean[BHN * D];

__device__ __forceinline__ void split_pack(float x, float y, uint32_t& hi, uint32_t& lo) {
    __nv_bfloat16 hx = __float2bfloat16(x), hy = __float2bfloat16(y);
    __nv_bfloat16 lx = __float2bfloat16(x - __bfloat162float(hx));
    __nv_bfloat16 ly = __float2bfloat16(y - __bfloat162float(hy));
    hi = (uint32_t)__bfloat16_as_ushort(hx) | ((uint32_t)__bfloat16_as_ushort(hy) << 16);
    lo = (uint32_t)__bfloat16_as_ushort(lx) | ((uint32_t)__bfloat16_as_ushort(ly) << 16);
}

#define MMA_BF16(cr, a, b0v, b1v)                                                  \
    asm volatile(                                                                  \
        "mma.sync.aligned.m16n8k16.row.col.f32.bf16.bf16.f32 "                     \
        "{%0,%1,%2,%3},{%4,%5,%6,%7},{%8,%9},{%0,%1,%2,%3};"                       \
        : "+f"((cr)[0]), "+f"((cr)[1]), "+f"((cr)[2]), "+f"((cr)[3])               \
        : "r"((a)[0]), "r"((a)[1]), "r"((a)[2]), "r"((a)[3]), "r"(b0v), "r"(b1v))

// ---------------------------------------------------------------------------
// Prologue 1: split K -> bf16 hi/lo (same layout), V -> transposed bf16 hi/lo.
// ---------------------------------------------------------------------------
__global__ void split_kernel(const float* __restrict__ k, const float* __restrict__ v) {
    const int bh = blockIdx.y, kb = blockIdx.x;   // 64-key block
    const int tid = threadIdx.x;
    __shared__ float sv[64][65];
    const float* kp = k + ((size_t)bh * L + kb * 64) * D;
    const float* vp = v + ((size_t)bh * L + kb * 64) * D;
    for (int i = tid; i < 4096; i += NT) {
        int r = i >> 6, d = i & 63;
        float x = kp[r * 64 + d];
        __nv_bfloat16 h = __float2bfloat16(x);
        size_t o = ((size_t)bh * L + kb * 64 + r) * 64 + d;
        g_khi[o] = h;
        g_klo[o] = __float2bfloat16(x - __bfloat162float(h));
        sv[r][d] = vp[r * 64 + d];
    }
    __syncthreads();
    for (int i = tid; i < 4096; i += NT) {
        int d = i >> 6, key = i & 63;
        float x = sv[key][d];
        __nv_bfloat16 h = __float2bfloat16(x);
        size_t o = ((size_t)bh * D + d) * L + kb * 64 + key;
        g_vthi[o] = h;
        g_vtlo[o] = __float2bfloat16(x - __bfloat162float(h));
    }
}

// ---------------------------------------------------------------------------
// Prologue 2: per-(b,h) mean of values (degenerate all-masked rows are
// uniform softmax over ALL 2048 keys in the reference).
// ---------------------------------------------------------------------------
__global__ void vmean_kernel(const float* __restrict__ v) {
    int bh = blockIdx.x;
    int d = threadIdx.x & 63;
    int grp = threadIdx.x >> 6;
    const float* vp = v + (size_t)bh * L * D;
    float s = 0.f;
    for (int kk = grp; kk < L; kk += 4) s += vp[(size_t)kk * D + d];
    __shared__ float red[4][64];
    red[grp][d] = s;
    __syncthreads();
    if (grp == 0)
        g_vmean[bh * D + d] = (red[0][d] + red[1][d] + red[2][d] + red[3][d]) * (1.0f / (float)L);
}

// ---------------------------------------------------------------------------
// Main: flash attention via mma.sync bf16 (split hi/lo, 3 passes per GEMM).
// Grid (16, 32); 256 threads = 8 warps; warp w owns q-rows [w*16, w*16+16).
// ---------------------------------------------------------------------------
__global__ void __launch_bounds__(NT, 2)
attn_hmma(const float* __restrict__ q, const int* __restrict__ qmask,
          const int* __restrict__ vmask, const float* __restrict__ bias,
          float* __restrict__ out)
{
    __shared__ __align__(16) __nv_bfloat16 sKhi[64][72];
    __shared__ __align__(16) __nv_bfloat16 sKlo[64][72];
    __shared__ __align__(16) __nv_bfloat16 sVhi[64][72];
    __shared__ __align__(16) __nv_bfloat16 sVlo[64][72];
    __shared__ int vmk[64];

    const int qt = (int)gridDim.x - 1 - (int)blockIdx.x;   // heavy-first
    const int bh = blockIdx.y;
    const int q0 = qt * 128;
    const int nk = 2 * (qt + 1);

    const int tid = threadIdx.x;
    const int w = tid >> 5, lane = tid & 31;
    const int g = lane >> 2, c = lane & 3;
    const int rg = q0 + w * 16 + g;       // global q-row (first of the pair)

    // ---- Q fragments (A operand, hi/lo), direct from gmem ----
    uint32_t Ahi[16], Alo[16];
    {
        const float* qp0 = q + ((size_t)bh * L + rg) * D;
        const float* qp8 = qp0 + 8 * D;
        #pragma unroll
        for (int ks = 0; ks < 4; ++ks)
            #pragma unroll
            for (int m = 0; m < 2; ++m) {
                int col = ks * 16 + 2 * c + 8 * m;
                float2 x0 = *(const float2*)(qp0 + col);
                float2 x8 = *(const float2*)(qp8 + col);
                split_pack(x0.x, x0.y, Ahi[ks * 4 + 2 * m], Alo[ks * 4 + 2 * m]);
                split_pack(x8.x, x8.y, Ahi[ks * 4 + 2 * m + 1], Alo[ks * 4 + 2 * m + 1]);
            }
    }

    float o[32];
    #pragma unroll
    for (int i = 0; i < 32; ++i) o[i] = 0.f;
    float Lr0 = 0.f, Lr8 = 0.f;

    const __nv_bfloat16* khB = g_khi + ((size_t)bh * L) * 64;
    const __nv_bfloat16* klB = g_klo + ((size_t)bh * L) * 64;
    const __nv_bfloat16* vhB = g_vthi + (size_t)bh * D * L;
    const __nv_bfloat16* vlB = g_vtlo + (size_t)bh * D * L;

    for (int t = 0; t < nk; ++t) {
        const int k0 = t * 64;
        __syncthreads();
        // ---- fill smem tiles (pure bf16 copies) ----
        for (int i = tid; i < 512; i += NT) {
            int r = i >> 3, s = i & 7;
            *(uint4*)&sKhi[r][s * 8] = *(const uint4*)(khB + ((size_t)(k0 + r)) * 64 + s * 8);
            *(uint4*)&sKlo[r][s * 8] = *(const uint4*)(klB + ((size_t)(k0 + r)) * 64 + s * 8);
            *(uint4*)&sVhi[r][s * 8] = *(const uint4*)(vhB + (size_t)r * L + k0 + s * 8);
            *(uint4*)&sVlo[r][s * 8] = *(const uint4*)(vlB + (size_t)r * L + k0 + s * 8);
        }
        if (tid < 64) vmk[tid] = vmask[(size_t)bh * L + k0 + tid];
        __syncthreads();

        const bool needC = (t >= nk - 2);
        const float* bp0 = bias + ((size_t)(bh * L + rg)) * L + k0;
        const float* bp8 = bp0 + (size_t)8 * L;

        #pragma unroll
        for (int kk = 0; kk < 4; ++kk) {
            // ---- S fragments for j = 2kk, 2kk+1 ----
            float s4[2][4];
            #pragma unroll
            for (int jj = 0; jj < 2; ++jj) {
                s4[jj][0] = s4[jj][1] = s4[jj][2] = s4[jj][3] = 0.f;
                int key = (2 * kk + jj) * 8 + g;
                #pragma unroll
                for (int ks = 0; ks < 4; ++ks) {
                    uint32_t bh0 = *(const uint32_t*)&sKhi[key][ks * 16 + 2 * c];
                    uint32_t bh1 = *(const uint32_t*)&sKhi[key][ks * 16 + 2 * c + 8];
                    uint32_t bl0 = *(const uint32_t*)&sKlo[key][ks * 16 + 2 * c];
                    uint32_t bl1 = *(const uint32_t*)&sKlo[key][ks * 16 + 2 * c + 8];
                    MMA_BF16(s4[jj], &Ahi[ks * 4], bh0, bh1);
                    MMA_BF16(s4[jj], &Ahi[ks * 4], bl0, bl1);
                    MMA_BF16(s4[jj], &Alo[ks * 4], bh0, bh1);
                }
            }
            // ---- softmax (no max-shift) + pack P hi/lo ----
            uint32_t phi[4], plo[4];
            #pragma unroll
            for (int jj = 0; jj < 2; ++jj) {
                int n0 = (2 * kk + jj) * 8 + 2 * c;
                int cg = k0 + n0;
                int m0 = vmk[n0], m1 = vmk[n0 + 1];
                float2 b0 = *(const float2*)(bp0 + n0);
                float2 b8 = *(const float2*)(bp8 + n0);
                bool ok00 = m0 && (!needC || (cg     <= rg));
                bool ok01 = m1 && (!needC || (cg + 1 <= rg));
                bool ok80 = m0 && (!needC || (cg     <= rg + 8));
                bool ok81 = m1 && (!needC || (cg + 1 <= rg + 8));
                float p00 = ok00 ? __expf(s4[jj][0] * 0.125f + b0.x) : 0.f;
                float p01 = ok01 ? __expf(s4[jj][1] * 0.125f + b0.y) : 0.f;
                float p80 = ok80 ? __expf(s4[jj][2] * 0.125f + b8.x) : 0.f;
                float p81 = ok81 ? __expf(s4[jj][3] * 0.125f + b8.y) : 0.f;
                Lr0 += p00 + p01;
                Lr8 += p80 + p81;
                split_pack(p00, p01, phi[jj * 2],     plo[jj * 2]);
                split_pack(p80, p81, phi[jj * 2 + 1], plo[jj * 2 + 1]);
            }
            // ---- O += P * V for this k16 step ----
            #pragma unroll
            for (int j2 = 0; j2 < 8; ++j2) {
                int vd = j2 * 8 + g;
                uint32_t vh0 = *(const uint32_t*)&sVhi[vd][kk * 16 + 2 * c];
                uint32_t vh1 = *(const uint32_t*)&sVhi[vd][kk * 16 + 2 * c + 8];
                uint32_t vl0 = *(const uint32_t*)&sVlo[vd][kk * 16 + 2 * c];
                uint32_t vl1 = *(const uint32_t*)&sVlo[vd][kk * 16 + 2 * c + 8];
                MMA_BF16(&o[j2 * 4], phi, vh0, vh1);
                MMA_BF16(&o[j2 * 4], phi, vl0, vl1);
                MMA_BF16(&o[j2 * 4], plo, vh0, vh1);
            }
        }
    }

    // ---- epilogue: row sums, normalize, degenerate/qmask, store ----
    float l0 = Lr0, l8 = Lr8;
    l0 += __shfl_xor_sync(0xffffffffu, l0, 1);
    l0 += __shfl_xor_sync(0xffffffffu, l0, 2);
    l8 += __shfl_xor_sync(0xffffffffu, l8, 1);
    l8 += __shfl_xor_sync(0xffffffffu, l8, 2);

    const int qm0 = qmask[(size_t)bh * L + rg];
    const int qm8 = qmask[(size_t)bh * L + rg + 8];
    const bool dg0 = (l0 == 0.f), dg8 = (l8 == 0.f);
    const float i0 = dg0 ? 0.f : 1.f / l0;
    const float i8 = dg8 ? 0.f : 1.f / l8;

    float* op0 = out + ((size_t)bh * L + rg) * D;
    float* op8 = op0 + 8 * D;
    #pragma unroll
    for (int j2 = 0; j2 < 8; ++j2) {
        int d0 = j2 * 8 + 2 * c;
        float v00 = dg0 ? g_vmean[bh * D + d0]     : o[j2 * 4 + 0] * i0;
        float v01 = dg0 ? g_vmean[bh * D + d0 + 1] : o[j2 * 4 + 1] * i0;
        float v80 = dg8 ? g_vmean[bh * D + d0]     : o[j2 * 4 + 2] * i8;
        float v81 = dg8 ? g_vmean[bh * D + d0 + 1] : o[j2 * 4 + 3] * i8;
        if (!qm0) { v00 = 0.f; v01 = 0.f; }
        if (!qm8) { v80 = 0.f; v81 = 0.f; }
        float2 r0 = {v00, v01}, r8 = {v80, v81};
        *(float2*)(op0 + d0) = r0;
        *(float2*)(op8 + d0) = r8;
    }
}

// ---------------------------------------------------------------------------
extern "C" void kernel_launch(void* const* d_in, const int* in_sizes, int n_in,
                              void* d_out, int out_size)
{
    const float* q = (const float*)d_in[0];
    const float* k = (const float*)d_in[1];
    const float* v = (const float*)d_in[2];
    const int* qmask = (const int*)d_in[3];
    const int* vmask = (const int*)d_in[4];
    const float* bias = (const float*)d_in[5];
    float* out = (float*)d_out;

    dim3 sg(L / 64, BHN);
    split_kernel<<<sg, NT>>>(k, v);
    vmean_kernel<<<BHN, 256>>>(v);
    dim3 grid(L / 128, BHN);
    attn_hmma<<<grid, NT>>>(q, qmask, vmask, bias, out);
}

// round 17
// speedup vs baseline: 1.9241x; 1.1358x over previous
#include <cuda_runtime.h>
#include <cuda_bf16.h>
#include <math.h>
#include <stdint.h>

constexpr int B = 2, H = 16, L = 2048, D = 64, BHN = 32;
constexpr int NT = 256;

// smem layout (bytes) per buffer: Khi[64][72], Klo, Vhi, Vlo (bf16)
constexpr int ROWB   = 144;                 // 72 bf16 row stride
constexpr int ARRB   = 64 * ROWB;           // 9216
constexpr int BUFSZ  = 4 * ARRB;            // 36864
constexpr int OFF_V  = 2 * ARRB;            // VHI offset inside buffer
constexpr int OFF_VMK = 2 * BUFSZ;          // 73728, then 2*256 B of vmask
constexpr int SMEMSZ  = OFF_VMK + 512;      // 74240

// Pre-split K (row-major [bh][key][d]) and V^T ([bh][d][key]) as bf16 hi/lo.
__device__ __align__(16) __nv_bfloat16 g_khi[(size_t)BHN * L * D];
__device__ __align__(16) __nv_bfloat16 g_klo[(size_t)BHN * L * D];
__device__ __align__(16) __nv_bfloat16 g_vthi[(size_t)BHN * D * L];
__device__ __align__(16) __nv_bfloat16 g_vtlo[(size_t)BHN * D * L];
__device__ float g_vmean[BHN * D];

__device__ __forceinline__ uint32_t smem_u32(const void* p) {
    uint32_t a;
    asm("{ .reg .u64 t; cvta.to.shared.u64 t, %1; cvt.u32.u64 %0, t; }" : "=r"(a) : "l"(p));
    return a;
}
__device__ __forceinline__ void split_pack(float x, float y, uint32_t& hi, uint32_t& lo) {
    __nv_bfloat16 hx = __float2bfloat16(x), hy = __float2bfloat16(y);
    __nv_bfloat16 lx = __float2bfloat16(x - __bfloat162float(hx));
    __nv_bfloat16 ly = __float2bfloat16(y - __bfloat162float(hy));
    hi = (uint32_t)__bfloat16_as_ushort(hx) | ((uint32_t)__bfloat16_as_ushort(hy) << 16);
    lo = (uint32_t)__bfloat16_as_ushort(lx) | ((uint32_t)__bfloat16_as_ushort(ly) << 16);
}

#define MMA_BF16(cr, a, b0v, b1v)                                                  \
    asm volatile(                                                                  \
        "mma.sync.aligned.m16n8k16.row.col.f32.bf16.bf16.f32 "                     \
        "{%0,%1,%2,%3},{%4,%5,%6,%7},{%8,%9},{%0,%1,%2,%3};"                       \
        : "+f"((cr)[0]), "+f"((cr)[1]), "+f"((cr)[2]), "+f"((cr)[3])               \
        : "r"((a)[0]), "r"((a)[1]), "r"((a)[2]), "r"((a)[3]), "r"(b0v), "r"(b1v))

#define LDMX4(r0, r1, r2, r3, a)                                                   \
    asm volatile("ldmatrix.sync.aligned.m8n8.x4.shared.b16 {%0,%1,%2,%3}, [%4];"   \
        : "=r"(r0), "=r"(r1), "=r"(r2), "=r"(r3) : "r"(a))

#define CPA16(dst, src) \
    asm volatile("cp.async.cg.shared.global [%0], [%1], 16;" :: "r"(dst), "l"(src))
#define CP_COMMIT() asm volatile("cp.async.commit_group;" ::: "memory")
#define CP_WAIT0()  asm volatile("cp.async.wait_group 0;" ::: "memory")

// ---------------------------------------------------------------------------
// Prologue 1: split K -> bf16 hi/lo, V -> transposed bf16 hi/lo (vectorized).
// sv stride 68 floats = 272 B: 16B-aligned rows for the float4 staging store.
// ---------------------------------------------------------------------------
__global__ void split_kernel(const float* __restrict__ k, const float* __restrict__ v) {
    const int bh = blockIdx.y, kb = blockIdx.x;   // 64-key block
    const int tid = threadIdx.x;
    __shared__ __align__(16) float sv[64][68];
    const float* kp = k + ((size_t)bh * L + kb * 64) * D;
    const float* vp = v + ((size_t)bh * L + kb * 64) * D;
    for (int i = tid; i < 1024; i += NT) {        // 64 rows x 16 d4-chunks
        int r = i >> 4, d4 = (i & 15) * 4;
        float4 x = *(const float4*)(kp + r * 64 + d4);
        uint32_t h0, l0, h1, l1;
        split_pack(x.x, x.y, h0, l0);
        split_pack(x.z, x.w, h1, l1);
        size_t o = ((size_t)bh * L + kb * 64 + r) * 64 + d4;
        uint2 hh = {h0, h1}, ll = {l0, l1};
        *(uint2*)(g_khi + o) = hh;
        *(uint2*)(g_klo + o) = ll;
        float4 y = *(const float4*)(vp + r * 64 + d4);
        *(float4*)&sv[r][d4] = y;
    }
    __syncthreads();
    for (int i = tid; i < 512; i += NT) {         // 64 d x 8 key8-blocks
        int d = i >> 3, k8 = (i & 7) * 8;
        uint32_t hv[4], lv[4];
        #pragma unroll
        for (int j = 0; j < 4; ++j)
            split_pack(sv[k8 + 2 * j][d], sv[k8 + 2 * j + 1][d], hv[j], lv[j]);
        size_t o = ((size_t)bh * D + d) * L + kb * 64 + k8;
        uint4 hq = {hv[0], hv[1], hv[2], hv[3]};
        uint4 lq = {lv[0], lv[1], lv[2], lv[3]};
        *(uint4*)(g_vthi + o) = hq;
        *(uint4*)(g_vtlo + o) = lq;
    }
}

// ---------------------------------------------------------------------------
// Prologue 2: per-(b,h) mean of values (reference's all-masked rows softmax
// uniformly over ALL 2048 keys).
// ---------------------------------------------------------------------------
__global__ void vmean_kernel(const float* __restrict__ v) {
    int bh = blockIdx.x;
    int d = threadIdx.x & 63;
    int grp = threadIdx.x >> 6;
    const float* vp = v + (size_t)bh * L * D;
    float s = 0.f;
    for (int kk = grp; kk < L; kk += 4) s += vp[(size_t)kk * D + d];
    __shared__ float red[4][64];
    red[grp][d] = s;
    __syncthreads();
    if (grp == 0)
        g_vmean[bh * D + d] = (red[0][d] + red[1][d] + red[2][d] + red[3][d]) * (1.0f / (float)L);
}

// ---------------------------------------------------------------------------
// Issue async fill of one 64-key tile into buffer `buf`.
// ---------------------------------------------------------------------------
__device__ __forceinline__ void fill_async(
    uint32_t sb, int buf, const __nv_bfloat16* khB, const __nv_bfloat16* klB,
    const __nv_bfloat16* vhB, const __nv_bfloat16* vlB,
    const int* vmaskp, int k0, int tid)
{
    const uint32_t base = sb + buf * BUFSZ;
    for (int i = tid; i < 512; i += NT) {
        int r = i >> 3, s = i & 7;
        uint32_t drow = base + r * ROWB + s * 16;
        CPA16(drow,            (const char*)(khB + (size_t)(k0 + r) * 64 + s * 8));
        CPA16(drow + ARRB,     (const char*)(klB + (size_t)(k0 + r) * 64 + s * 8));
        CPA16(drow + OFF_V,    (const char*)(vhB + (size_t)r * L + k0 + s * 8));
        CPA16(drow + OFF_V + ARRB, (const char*)(vlB + (size_t)r * L + k0 + s * 8));
    }
    if (tid < 16)
        CPA16(sb + OFF_VMK + buf * 256 + tid * 16, (const char*)(vmaskp + k0 + tid * 4));
}

// ---------------------------------------------------------------------------
// Main: flash attention via mma.sync bf16 (split hi/lo, 3 passes per GEMM),
// ldmatrix B-fragments, cp.async double-buffered tiles, pipelined bias.
// ---------------------------------------------------------------------------
extern __shared__ char smem[];

__global__ void __launch_bounds__(NT, 2)
attn_hmma(const float* __restrict__ q, const int* __restrict__ qmask,
          const int* __restrict__ vmask, const float* __restrict__ bias,
          float* __restrict__ out)
{
    const int qt = (int)gridDim.x - 1 - (int)blockIdx.x;   // heavy-first
    const int bh = blockIdx.y;
    const int q0 = qt * 128;
    const int nk = 2 * (qt + 1);

    const uint32_t sb = smem_u32(smem);
    const int tid = threadIdx.x;
    const int w = tid >> 5, lane = tid & 31;
    const int g = lane >> 2, c = lane & 3;
    const int rg = q0 + w * 16 + g;
    // ldmatrix per-lane row offset: matrices {Khi b0, Khi b1, Klo b0, Klo b1}
    const int mat = lane >> 3, mr = lane & 7;
    const uint32_t lmoff = (mat >= 2 ? (uint32_t)ARRB : 0u) + mr * ROWB + (mat & 1) * 16;

    const __nv_bfloat16* khB = g_khi + (size_t)bh * L * 64;
    const __nv_bfloat16* klB = g_klo + (size_t)bh * L * 64;
    const __nv_bfloat16* vhB = g_vthi + (size_t)bh * D * L;
    const __nv_bfloat16* vlB = g_vtlo + (size_t)bh * D * L;
    const int* vmaskp = vmask + (size_t)bh * L;

    // prefetch tile 0
    fill_async(sb, 0, khB, klB, vhB, vlB, vmaskp, 0, tid);
    CP_COMMIT();

    // ---- Q fragments (A operand, hi/lo) ----
    uint32_t Ahi[16], Alo[16];
    {
        const float* qp0 = q + ((size_t)bh * L + rg) * D;
        const float* qp8 = qp0 + 8 * D;
        #pragma unroll
        for (int ks = 0; ks < 4; ++ks)
            #pragma unroll
            for (int m = 0; m < 2; ++m) {
                int col = ks * 16 + 2 * c + 8 * m;
                float2 x0 = *(const float2*)(qp0 + col);
                float2 x8 = *(const float2*)(qp8 + col);
                split_pack(x0.x, x0.y, Ahi[ks * 4 + 2 * m], Alo[ks * 4 + 2 * m]);
                split_pack(x8.x, x8.y, Ahi[ks * 4 + 2 * m + 1], Alo[ks * 4 + 2 * m + 1]);
            }
    }

    float o[32];
    #pragma unroll
    for (int i = 0; i < 32; ++i) o[i] = 0.f;
    float Lr0 = 0.f, Lr8 = 0.f;

    for (int t = 0; t < nk; ++t) {
        const int buf = t & 1;
        const uint32_t bufoff = buf * BUFSZ;
        CP_WAIT0();
        __syncthreads();
        if (t + 1 < nk) {
            fill_async(sb, (t + 1) & 1, khB, klB, vhB, vlB, vmaskp, (t + 1) * 64, tid);
            CP_COMMIT();
        }

        const int k0 = t * 64;
        const bool needC = (t >= nk - 2);
        const int* vmk = (const int*)(smem + OFF_VMK + buf * 256);
        const float* bp0 = bias + ((size_t)(bh * L + rg)) * L + k0;
        const float* bp8 = bp0 + (size_t)8 * L;

        // bias pipeline: cur regs for kk, next loaded one step ahead
        float2 c0[2], c8[2], nn0[2], nn8[2];
        c0[0] = *(const float2*)(bp0 + 2 * c);
        c0[1] = *(const float2*)(bp0 + 8 + 2 * c);
        c8[0] = *(const float2*)(bp8 + 2 * c);
        c8[1] = *(const float2*)(bp8 + 8 + 2 * c);

        #pragma unroll
        for (int kk = 0; kk < 4; ++kk) {
            if (kk < 3) {
                nn0[0] = *(const float2*)(bp0 + (2 * kk + 2) * 8 + 2 * c);
                nn0[1] = *(const float2*)(bp0 + (2 * kk + 3) * 8 + 2 * c);
                nn8[0] = *(const float2*)(bp8 + (2 * kk + 2) * 8 + 2 * c);
                nn8[1] = *(const float2*)(bp8 + (2 * kk + 3) * 8 + 2 * c);
            }
            // ---- S fragments for j = 2kk, 2kk+1 ----
            float s4[2][4];
            #pragma unroll
            for (int jj = 0; jj < 2; ++jj) {
                s4[jj][0] = s4[jj][1] = s4[jj][2] = s4[jj][3] = 0.f;
                const uint32_t kbase = sb + bufoff + lmoff + (uint32_t)(2 * kk + jj) * (8 * ROWB);
                #pragma unroll
                for (int ks = 0; ks < 4; ++ks) {
                    uint32_t b0, b1, b2, b3;
                    LDMX4(b0, b1, b2, b3, kbase + ks * 32);
                    MMA_BF16(s4[jj], &Ahi[ks * 4], b0, b1);
                    MMA_BF16(s4[jj], &Ahi[ks * 4], b2, b3);
                    MMA_BF16(s4[jj], &Alo[ks * 4], b0, b1);
                }
            }
            // ---- softmax (no max-shift; masked -> 0) + pack P hi/lo ----
            uint32_t phi[4], plo[4];
            #pragma unroll
            for (int jj = 0; jj < 2; ++jj) {
                int n0 = (2 * kk + jj) * 8 + 2 * c;
                int cg = k0 + n0;
                int m0 = vmk[n0], m1 = vmk[n0 + 1];
                bool ok00 = m0 && (!needC || (cg     <= rg));
                bool ok01 = m1 && (!needC || (cg + 1 <= rg));
                bool ok80 = m0 && (!needC || (cg     <= rg + 8));
                bool ok81 = m1 && (!needC || (cg + 1 <= rg + 8));
                float p00 = ok00 ? __expf(s4[jj][0] * 0.125f + c0[jj].x) : 0.f;
                float p01 = ok01 ? __expf(s4[jj][1] * 0.125f + c0[jj].y) : 0.f;
                float p80 = ok80 ? __expf(s4[jj][2] * 0.125f + c8[jj].x) : 0.f;
                float p81 = ok81 ? __expf(s4[jj][3] * 0.125f + c8[jj].y) : 0.f;
                Lr0 += p00 + p01;
                Lr8 += p80 + p81;
                split_pack(p00, p01, phi[jj * 2],     plo[jj * 2]);
                split_pack(p80, p81, phi[jj * 2 + 1], plo[jj * 2 + 1]);
            }
            // ---- O += P * V for this k16 step ----
            const uint32_t vbase = sb + bufoff + OFF_V + lmoff + kk * 32;
            #pragma unroll
            for (int j2 = 0; j2 < 8; ++j2) {
                uint32_t v0, v1, v2, v3;
                LDMX4(v0, v1, v2, v3, vbase + (uint32_t)j2 * (8 * ROWB));
                MMA_BF16(&o[j2 * 4], phi, v0, v1);
                MMA_BF16(&o[j2 * 4], phi, v2, v3);
                MMA_BF16(&o[j2 * 4], plo, v0, v1);
            }
            if (kk < 3) {
                c0[0] = nn0[0]; c0[1] = nn0[1];
                c8[0] = nn8[0]; c8[1] = nn8[1];
            }
        }
    }

    // ---- epilogue ----
    float l0 = Lr0, l8 = Lr8;
    l0 += __shfl_xor_sync(0xffffffffu, l0, 1);
    l0 += __shfl_xor_sync(0xffffffffu, l0, 2);
    l8 += __shfl_xor_sync(0xffffffffu, l8, 1);
    l8 += __shfl_xor_sync(0xffffffffu, l8, 2);

    const int qm0 = qmask[(size_t)bh * L + rg];
    const int qm8 = qmask[(size_t)bh * L + rg + 8];
    const bool dg0 = (l0 == 0.f), dg8 = (l8 == 0.f);
    const float i0 = dg0 ? 0.f : 1.f / l0;
    const float i8 = dg8 ? 0.f : 1.f / l8;

    float* op0 = out + ((size_t)bh * L + rg) * D;
    float* op8 = op0 + 8 * D;
    #pragma unroll
    for (int j2 = 0; j2 < 8; ++j2) {
        int d0 = j2 * 8 + 2 * c;
        float v00 = dg0 ? g_vmean[bh * D + d0]     : o[j2 * 4 + 0] * i0;
        float v01 = dg0 ? g_vmean[bh * D + d0 + 1] : o[j2 * 4 + 1] * i0;
        float v80 = dg8 ? g_vmean[bh * D + d0]     : o[j2 * 4 + 2] * i8;
        float v81 = dg8 ? g_vmean[bh * D + d0 + 1] : o[j2 * 4 + 3] * i8;
        if (!qm0) { v00 = 0.f; v01 = 0.f; }
        if (!qm8) { v80 = 0.f; v81 = 0.f; }
        float2 r0 = {v00, v01}, r8 = {v80, v81};
        *(float2*)(op0 + d0) = r0;
        *(float2*)(op8 + d0) = r8;
    }
}

// ---------------------------------------------------------------------------
extern "C" void kernel_launch(void* const* d_in, const int* in_sizes, int n_in,
                              void* d_out, int out_size)
{
    const float* q = (const float*)d_in[0];
    const float* k = (const float*)d_in[1];
    const float* v = (const float*)d_in[2];
    const int* qmask = (const int*)d_in[3];
    const int* vmask = (const int*)d_in[4];
    const float* bias = (const float*)d_in[5];
    float* out = (float*)d_out;

    cudaFuncSetAttribute(attn_hmma, cudaFuncAttributeMaxDynamicSharedMemorySize, SMEMSZ);

    dim3 sg(L / 64, BHN);
    split_kernel<<<sg, NT>>>(k, v);
    vmean_kernel<<<BHN, 256>>>(v);
    dim3 grid(L / 128, BHN);
    attn_hmma<<<grid, NT, SMEMSZ>>>(q, qmask, vmask, bias, out);
}